// round 15
// baseline (speedup 1.0000x reference)
#include <cuda_runtime.h>
#include <cuda_bf16.h>
#include <cstdint>

// Local 5x5 window dot-product attention. B=2, H=W=256, C=BIN=32.
// R15 = R13 frame (64-thr blocks, 3/SM, 16-plane channel-major smem,
// single staging burst, ONE barrier) with __expf replaced by a packed
// f32x2 polynomial exp on the FMA pipe:
//   e^x = 2^y, y = x*log2e; i = rint(y) via +1.5*2^23 trick (bits of t
//   give i directly); 2^f by degree-5 Taylor (rel err ~2.4e-6, f in
//   [-.5,.5]); scale by 2^i rebuilt as ((tbits+K)<<23) on the ALU pipe.
// Theory: the ~33.3us plateau across ALL designs is the hidden MUFU pipe
// (3.28M EX2 ops = ~44k cyc/SM at rt 8/SMSP). This removes every MUFU op
// from the hot path (25 packed exps per thread, pairs (a0[k],a1[k])).

#define Hh 256
#define Ww 256
#define TW 16
#define TH 8
#define HW 20
#define HHALO 12
#define NPIX (HHALO * HW)          // 240
#define PL 964
#define NPLANES 16
#define NTHREADS 64
#define SMEM_BYTES (NPLANES * PL * 4)   // 61696

typedef unsigned long long u64;

#define MUL2(d, a, b)    asm("mul.rn.f32x2 %0, %1, %2;"     : "=l"(d) : "l"(a), "l"(b))
#define FMA2(d, a, b, c) asm("fma.rn.f32x2 %0, %1, %2, %3;" : "=l"(d) : "l"(a), "l"(b), "l"(c))
#define ADD2(d, a, b)    asm("add.rn.f32x2 %0, %1, %2;"     : "=l"(d) : "l"(a), "l"(b))
#define PACK2(d, x)      asm("mov.b64 %0, {%1, %1};"        : "=l"(d) : "f"(x))
#define PACKAB(d, x, y)  asm("mov.b64 %0, {%1, %2};"        : "=l"(d) : "f"(x), "f"(y))
#define PACKU(d, x, y)   asm("mov.b64 %0, {%1, %2};"        : "=l"(d) : "r"(x), "r"(y))
#define UNPACK2(lo, hi, v) asm("mov.b64 {%0, %1}, %2;" : "=f"(lo), "=f"(hi) : "l"(v))
#define UNPACKU(lo, hi, v) asm("mov.b64 {%0, %1}, %2;" : "=r"(lo), "=r"(hi) : "l"(v))

extern __shared__ float s[];

__global__ __launch_bounds__(NTHREADS, 3)
void local_attn_kernel(const float* __restrict__ qmain,
                       const float* __restrict__ ref,
                       const float* __restrict__ refv,
                       float* __restrict__ out)
{
    const int tid = threadIdx.x;
    const int tx  = tid & (TW - 1);      // 0..15
    const int ty  = tid >> 4;            // 0..3 -> pixel rows 2ty, 2ty+1
    const int w0  = blockIdx.x * TW;
    const int h0  = blockIdx.y * TH;
    const int b   = blockIdx.z;

    const int gh0 = h0 + 2 * ty;
    const size_t pix0 = (((size_t)b * Hh + gh0) * Ww + (w0 + tx));

    // ---- stage BOTH halos (20x12 px each) into the 16-plane buffer ----
    #pragma unroll
    for (int it = 0; it < (NPIX * 8) / NTHREADS; it++) {   // 30 iters: ref
        const int idx = it * NTHREADS + tid;
        const int p  = idx >> 3;
        const int c4 = idx & 7;
        const int r  = p / HW;
        const int c  = p - r * HW;
        const int gh = h0 + r - 2;
        const int gw = w0 + c - 2;
        float4 v = make_float4(0.f, 0.f, 0.f, 0.f);
        if ((unsigned)gh < Hh && (unsigned)gw < Ww)
            v = *(const float4*)(ref + ((((size_t)b * Hh + gh) * Ww + gw) << 5) + (c4 << 2));
        *(float4*)(s + c4 * PL + (p << 2)) = v;
    }
    #pragma unroll
    for (int it = 0; it < (NPIX * 8) / NTHREADS; it++) {   // 30 iters: refv
        const int idx = it * NTHREADS + tid;
        const int p  = idx >> 3;
        const int c4 = idx & 7;
        const int r  = p / HW;
        const int c  = p - r * HW;
        const int gh = h0 + r - 2;
        const int gw = w0 + c - 2;
        float4 v = make_float4(0.f, 0.f, 0.f, 0.f);
        if ((unsigned)gh < Hh && (unsigned)gw < Ww)
            v = *(const float4*)(refv + ((((size_t)b * Hh + gh) * Ww + gw) << 5) + (c4 << 2));
        *(float4*)(s + (8 + c4) * PL + (p << 2)) = v;
    }

    // query vectors for both pixels (overlaps staging stores)
    ulonglong2 m0[8], m1[8];
    {
        const ulonglong2* mp0 = (const ulonglong2*)(qmain + (pix0 << 5));
        const ulonglong2* mp1 = (const ulonglong2*)((const float*)mp0 + (Ww << 5));
        #pragma unroll
        for (int k = 0; k < 8; k++) { m0[k] = mp0[k]; m1[k] = mp1[k]; }
    }
    __syncthreads();   // the ONLY barrier

    // ---- pass 1: 30 independent dots -> 50 logits (4-chain reductions) ----
    float a0[25], a1[25];
    #pragma unroll
    for (int dr = 0; dr < 6; dr++) {
        #pragma unroll
        for (int dj = 0; dj < 5; dj++) {
            const float* spf = s + (((2 * ty + dr) * HW + tx + dj) << 2);
            ulonglong2 vr[8];
            #pragma unroll
            for (int k = 0; k < 8; k++)
                vr[k] = *(const ulonglong2*)(spf + k * PL);
            if (dr < 5) {
                u64 c0, c1, c2, c3;
                MUL2(c0, m0[0].x, vr[0].x);
                MUL2(c1, m0[0].y, vr[0].y);
                MUL2(c2, m0[1].x, vr[1].x);
                MUL2(c3, m0[1].y, vr[1].y);
                FMA2(c0, m0[2].x, vr[2].x, c0);
                FMA2(c1, m0[2].y, vr[2].y, c1);
                FMA2(c2, m0[3].x, vr[3].x, c2);
                FMA2(c3, m0[3].y, vr[3].y, c3);
                FMA2(c0, m0[4].x, vr[4].x, c0);
                FMA2(c1, m0[4].y, vr[4].y, c1);
                FMA2(c2, m0[5].x, vr[5].x, c2);
                FMA2(c3, m0[5].y, vr[5].y, c3);
                FMA2(c0, m0[6].x, vr[6].x, c0);
                FMA2(c1, m0[6].y, vr[6].y, c1);
                FMA2(c2, m0[7].x, vr[7].x, c2);
                FMA2(c3, m0[7].y, vr[7].y, c3);
                ADD2(c0, c0, c1);
                ADD2(c2, c2, c3);
                ADD2(c0, c0, c2);
                float lo, hi; UNPACK2(lo, hi, c0);
                a0[dr * 5 + dj] = lo + hi;
            }
            if (dr >= 1) {
                u64 c0, c1, c2, c3;
                MUL2(c0, m1[0].x, vr[0].x);
                MUL2(c1, m1[0].y, vr[0].y);
                MUL2(c2, m1[1].x, vr[1].x);
                MUL2(c3, m1[1].y, vr[1].y);
                FMA2(c0, m1[2].x, vr[2].x, c0);
                FMA2(c1, m1[2].y, vr[2].y, c1);
                FMA2(c2, m1[3].x, vr[3].x, c2);
                FMA2(c3, m1[3].y, vr[3].y, c3);
                FMA2(c0, m1[4].x, vr[4].x, c0);
                FMA2(c1, m1[4].y, vr[4].y, c1);
                FMA2(c2, m1[5].x, vr[5].x, c2);
                FMA2(c3, m1[5].y, vr[5].y, c3);
                FMA2(c0, m1[6].x, vr[6].x, c0);
                FMA2(c1, m1[6].y, vr[6].y, c1);
                FMA2(c2, m1[7].x, vr[7].x, c2);
                FMA2(c3, m1[7].y, vr[7].y, c3);
                ADD2(c0, c0, c1);
                ADD2(c2, c2, c3);
                ADD2(c0, c0, c2);
                float lo, hi; UNPACK2(lo, hi, c0);
                a1[(dr - 1) * 5 + dj] = lo + hi;
            }
        }
    }

    // ---- packed polynomial exp on the FMA pipe (NO MUFU) ----
    // e^x = 2^(x*log2e); rint via +1.5*2^23; 2^f deg-5 Taylor; scale by
    // 2^i rebuilt from the rint trick's mantissa bits ((tbits+K)<<23).
    u64 pL2E, pC, pCn, pN1, pc5, pc4, pc3, pc2, pc1, pOne, ssum2;
    PACK2(pL2E, 1.4426950408889634f);
    PACK2(pC,   12582912.0f);        // 1.5 * 2^23
    PACK2(pCn, -12582912.0f);
    PACK2(pN1, -1.0f);
    PACK2(pc5, 0.0013333558f);
    PACK2(pc4, 0.0096181291f);
    PACK2(pc3, 0.0555041087f);
    PACK2(pc2, 0.2402265070f);
    PACK2(pc1, 0.6931471806f);
    PACK2(pOne, 1.0f);
    ssum2 = 0ULL;
    const uint32_t KADD = 0xB4C0007Fu;   // (127 - 0x4B400000) mod 2^32

    #pragma unroll
    for (int k = 0; k < 25; k++) {
        u64 x2, y, t, fi, f, p;
        PACKAB(x2, a0[k], a1[k]);
        MUL2(y, x2, pL2E);
        ADD2(t, y, pC);          // bits(t) = 0x4B400000 + i (per half)
        ADD2(fi, t, pCn);        // i as float
        FMA2(f, fi, pN1, y);     // f = y - i, in [-0.5, 0.5]
        FMA2(p, pc5, f, pc4);
        FMA2(p, p, f, pc3);
        FMA2(p, p, f, pc2);
        FMA2(p, p, f, pc1);
        FMA2(p, p, f, pOne);     // 2^f
        uint32_t tlo, thi;
        UNPACKU(tlo, thi, t);
        const uint32_t slo = (tlo + KADD) << 23;   // bits of 2^i (half 0)
        const uint32_t shi = (thi + KADD) << 23;   // bits of 2^i (half 1)
        u64 sc, e2;
        PACKU(sc, slo, shi);
        MUL2(e2, p, sc);         // e^x pair
        ADD2(ssum2, ssum2, e2);  // packed softmax sums
        float e0, e1; UNPACK2(e0, e1, e2);
        a0[k] = e0; a1[k] = e1;
    }
    float s0, s1; UNPACK2(s0, s1, ssum2);

    // ---- pass 2: weighted accumulation (weights already in regs) ----
    u64 o0p[16], o1p[16];
    #pragma unroll
    for (int k = 0; k < 16; k++) { o0p[k] = 0ULL; o1p[k] = 0ULL; }

    #pragma unroll
    for (int dr = 0; dr < 6; dr++) {
        #pragma unroll
        for (int dj = 0; dj < 5; dj++) {
            const float* spf = s + (((2 * ty + dr) * HW + tx + dj) << 2);
            ulonglong2 vv[8];
            #pragma unroll
            for (int k = 0; k < 8; k++)
                vv[k] = *(const ulonglong2*)(spf + (8 + k) * PL);
            if (dr < 5) {
                u64 wp; PACK2(wp, a0[dr * 5 + dj]);
                #pragma unroll
                for (int k = 0; k < 8; k++) {
                    FMA2(o0p[2 * k],     wp, vv[k].x, o0p[2 * k]);
                    FMA2(o0p[2 * k + 1], wp, vv[k].y, o0p[2 * k + 1]);
                }
            }
            if (dr >= 1) {
                u64 wp; PACK2(wp, a1[(dr - 1) * 5 + dj]);
                #pragma unroll
                for (int k = 0; k < 8; k++) {
                    FMA2(o1p[2 * k],     wp, vv[k].x, o1p[2 * k]);
                    FMA2(o1p[2 * k + 1], wp, vv[k].y, o1p[2 * k + 1]);
                }
            }
        }
    }

    // ---- normalize and store ----
    float* op0 = out + (pix0 << 5);
    float* op1 = op0 + (Ww << 5);
    u64 i0p, i1p;
    PACK2(i0p, 1.f / s0);
    PACK2(i1p, 1.f / s1);
    #pragma unroll
    for (int k = 0; k < 8; k++) {
        ulonglong2 r0, r1;
        MUL2(r0.x, o0p[2 * k],     i0p);
        MUL2(r0.y, o0p[2 * k + 1], i0p);
        MUL2(r1.x, o1p[2 * k],     i1p);
        MUL2(r1.y, o1p[2 * k + 1], i1p);
        *(ulonglong2*)(op0 + (k << 2)) = r0;
        *(ulonglong2*)(op1 + (k << 2)) = r1;
    }
}

extern "C" void kernel_launch(void* const* d_in, const int* in_sizes, int n_in,
                              void* d_out, int out_size)
{
    const float* qmain = (const float*)d_in[0];
    const float* ref   = (const float*)d_in[1];
    const float* refv  = (const float*)d_in[2];
    float* out = (float*)d_out;

    cudaFuncSetAttribute(local_attn_kernel,
                         cudaFuncAttributeMaxDynamicSharedMemorySize, SMEM_BYTES);

    dim3 grid(Ww / TW, Hh / TH, 2);   // (16, 32, 2) = 1024 blocks
    dim3 block(NTHREADS);
    local_attn_kernel<<<grid, block, SMEM_BYTES>>>(qmain, ref, refv, out);
}